// round 8
// baseline (speedup 1.0000x reference)
#include <cuda_runtime.h>
#include <cuda_bf16.h>
#include <cstdint>

#define NN 50000
#define NE 800000
#define KF 128      // IN_FEAT
#define NH 4        // heads
#define FD 16       // out feat per head
#define HF 64       // NH*FD
#define NEG 0.2f

// Scratch (device globals: allocation-free). float4 typing guarantees 16B alignment.
__device__ float4 g_h[NN * 16];   // h[n][64] as 16 float4 per node
__device__ float4 g_es[NN];       // e_src per node, 4 heads
__device__ float4 g_ed[NN];       // e_dst per node, 4 heads
__device__ int    g_is64;         // 1 if edge_index is int64, else 0 (int32)

// ---------------------------------------------------------------------------
// Kernel 1 (fused): out-zeroing + dtype probe + h = x@W + attention logits.
// ---------------------------------------------------------------------------
__global__ void __launch_bounds__(256) gemm_logits_kernel(
    const float* __restrict__ x,
    const float* __restrict__ W,
    const float* __restrict__ a,
    const void* __restrict__ ei_raw,
    float* __restrict__ out)
{
    const int tid = threadIdx.x;

    // ---- dtype probe (block 0 only; consumed by the NEXT kernel) ----
    if (blockIdx.x == 0) {
        const long long* e64 = (const long long*)ei_raw;
        bool ok = true;
        #pragma unroll
        for (int i = 0; i < 4; i++) {
            long long v = e64[tid * 4 + i];
            if (v < 0 || v >= NN) ok = false;
        }
        __shared__ int allok;
        if (tid == 0) allok = 1;
        __syncthreads();
        if (!ok) atomicAnd(&allok, 0);
        __syncthreads();
        if (tid == 0) g_is64 = allok;
    }

    // ---- zero the output (edge kernel reds into it; runs strictly after) ----
    {
        float4* o4 = reinterpret_cast<float4*>(out);
        const float4 z = make_float4(0.f, 0.f, 0.f, 0.f);
        for (int i = blockIdx.x * 256 + tid; i < NN * 16; i += gridDim.x * 256)
            o4[i] = z;
    }

    // ---- stage W in shared ----
    __shared__ float2 Ws[KF * 32];           // 32 KB; lane j owns cols 2j,2j+1
    __shared__ float4 xs[8][4][KF / 4];      // 16 KB; 4 x-rows per warp

    const float2* W2 = reinterpret_cast<const float2*>(W);
    for (int i = tid; i < KF * 32; i += 256) Ws[i] = W2[i];
    __syncthreads();

    const int lane = tid & 31;
    const int w    = tid >> 5;
    const int head = lane >> 3;              // cols 2*lane -> head = lane/8
    const int f0   = (2 * lane) & 15;

    const float as0 = a[head * 32 + f0];
    const float as1 = a[head * 32 + f0 + 1];
    const float ad0 = a[head * 32 + 16 + f0];
    const float ad1 = a[head * 32 + 17 + f0];

    const int ngroups = NN / 4;              // 12500 exactly
    const int nwarps  = gridDim.x * 8;

    for (int grp = blockIdx.x * 8 + w; grp < ngroups; grp += nwarps) {
        const int n0 = grp * 4;

        #pragma unroll
        for (int j = 0; j < 4; j++)
            xs[w][j][lane] = reinterpret_cast<const float4*>(x + (size_t)(n0 + j) * KF)[lane];
        __syncwarp();

        float ax0 = 0.f, ay0 = 0.f, ax1 = 0.f, ay1 = 0.f;
        float ax2 = 0.f, ay2 = 0.f, ax3 = 0.f, ay3 = 0.f;

        #pragma unroll
        for (int kk = 0; kk < KF / 4; kk++) {
            const float4 xv0 = xs[w][0][kk];
            const float4 xv1 = xs[w][1][kk];
            const float4 xv2 = xs[w][2][kk];
            const float4 xv3 = xs[w][3][kk];
            const float xk0[4] = {xv0.x, xv0.y, xv0.z, xv0.w};
            const float xk1[4] = {xv1.x, xv1.y, xv1.z, xv1.w};
            const float xk2[4] = {xv2.x, xv2.y, xv2.z, xv2.w};
            const float xk3[4] = {xv3.x, xv3.y, xv3.z, xv3.w};
            #pragma unroll
            for (int dk = 0; dk < 4; dk++) {
                const float2 wv = Ws[(kk * 4 + dk) * 32 + lane];
                ax0 = fmaf(xk0[dk], wv.x, ax0);  ay0 = fmaf(xk0[dk], wv.y, ay0);
                ax1 = fmaf(xk1[dk], wv.x, ax1);  ay1 = fmaf(xk1[dk], wv.y, ay1);
                ax2 = fmaf(xk2[dk], wv.x, ax2);  ay2 = fmaf(xk2[dk], wv.y, ay2);
                ax3 = fmaf(xk3[dk], wv.x, ax3);  ay3 = fmaf(xk3[dk], wv.y, ay3);
            }
        }

        float2* h2 = reinterpret_cast<float2*>(g_h);
        h2[(size_t)(n0 + 0) * 32 + lane] = make_float2(ax0, ay0);
        h2[(size_t)(n0 + 1) * 32 + lane] = make_float2(ax1, ay1);
        h2[(size_t)(n0 + 2) * 32 + lane] = make_float2(ax2, ay2);
        h2[(size_t)(n0 + 3) * 32 + lane] = make_float2(ax3, ay3);

        float psv[4], pdv[4];
        psv[0] = ax0 * as0 + ay0 * as1;  pdv[0] = ax0 * ad0 + ay0 * ad1;
        psv[1] = ax1 * as0 + ay1 * as1;  pdv[1] = ax1 * ad0 + ay1 * ad1;
        psv[2] = ax2 * as0 + ay2 * as1;  pdv[2] = ax2 * ad0 + ay2 * ad1;
        psv[3] = ax3 * as0 + ay3 * as1;  pdv[3] = ax3 * ad0 + ay3 * ad1;
        #pragma unroll
        for (int j = 0; j < 4; j++) {
            float ps = psv[j], pd = pdv[j];
            ps += __shfl_xor_sync(0xffffffffu, ps, 1);
            ps += __shfl_xor_sync(0xffffffffu, ps, 2);
            ps += __shfl_xor_sync(0xffffffffu, ps, 4);
            pd += __shfl_xor_sync(0xffffffffu, pd, 1);
            pd += __shfl_xor_sync(0xffffffffu, pd, 2);
            pd += __shfl_xor_sync(0xffffffffu, pd, 4);
            if ((lane & 7) == 0) {
                reinterpret_cast<float*>(g_es)[(n0 + j) * 4 + head] = ps;
                reinterpret_cast<float*>(g_ed)[(n0 + j) * 4 + head] = pd;
            }
        }
        __syncwarp();   // xs reused next iteration
    }
}

// ---------------------------------------------------------------------------
// Kernel 2: per-edge softmax-weighted gather + vectorized scatter-add.
// 16 threads per edge; lane l owns output cols [4l, 4l+4) -> applied head h=l>>2.
// Cooperative softmax: within each aligned 4-lane quad (same edge), lane
// computes z/exp for head j=l&3 only; max/sum via shfl_xor trees; the
// applied head's p is fetched with one indexed shfl.
// ---------------------------------------------------------------------------
__device__ __forceinline__ void red_add_v4(float* p, float4 v) {
    asm volatile("red.global.add.v4.f32 [%0], {%1, %2, %3, %4};"
                 :: "l"(p), "f"(v.x), "f"(v.y), "f"(v.z), "f"(v.w)
                 : "memory");
}

__global__ void __launch_bounds__(256) edge_scatter_kernel(
    const void* __restrict__ ei_raw,
    float* __restrict__ out)
{
    const int gtid = blockIdx.x * 256 + threadIdx.x;
    const int e = gtid >> 4;
    if (e >= NE) return;
    const int l  = gtid & 15;         // lane within edge group
    const int wl = threadIdx.x & 31;  // lane within warp (for shfl indexing)

    int src, dst;
    if (g_is64) {
        const long long* e64 = (const long long*)ei_raw;
        src = (int)e64[e];
        dst = (int)e64[NE + e];
    } else {
        const int* e32 = (const int*)ei_raw;
        src = e32[e];
        dst = e32[NE + e];
    }

    const int j = l & 3;              // head this lane computes softmax term for
    const int h = l >> 2;             // head this lane applies to features

    // scalar logit loads (quad covers all 4 heads of this edge)
    const float esj = reinterpret_cast<const float*>(g_es)[src * 4 + j];
    const float edj = reinterpret_cast<const float*>(g_ed)[dst * 4 + j];
    float z = esj + edj;
    z = z > 0.f ? z : NEG * z;

    // softmax across the aligned 4-lane quad
    const unsigned m32 = 0xffffffffu;
    float mx = z;
    mx = fmaxf(mx, __shfl_xor_sync(m32, mx, 1));
    mx = fmaxf(mx, __shfl_xor_sync(m32, mx, 2));
    const float p = __expf(z - mx);
    float s = p;
    s += __shfl_xor_sync(m32, s, 1);
    s += __shfl_xor_sync(m32, s, 2);

    // fetch p for the applied head h from lane (quad_base | h)
    const float ph = __shfl_sync(m32, p, (wl & ~3) | h);
    const float alpha = ph / s;

    // gather h[src] row chunk (coalesced 256B across the 16-lane group)
    const float4 hv = g_h[(size_t)src * 16 + l];
    float4 v = make_float4(alpha * hv.x, alpha * hv.y, alpha * hv.z, alpha * hv.w);

    red_add_v4(out + (size_t)dst * HF + 4 * l, v);
}

// ---------------------------------------------------------------------------
extern "C" void kernel_launch(void* const* d_in, const int* in_sizes, int n_in,
                              void* d_out, int out_size)
{
    const float* x  = (const float*)d_in[0];
    const void*  ei = (const void*)d_in[1];
    const float* W  = (const float*)d_in[2];
    const float* a  = (const float*)d_in[3];
    float* out = (float*)d_out;

    gemm_logits_kernel<<<592, 256>>>(x, W, a, ei, out);

    const int nthreads = NE * 16;
    edge_scatter_kernel<<<(nthreads + 255) / 256, 256>>>(ei, out);

    (void)in_sizes; (void)n_in; (void)out_size;
}